// round 13
// baseline (speedup 1.0000x reference)
#include <cuda_runtime.h>
#include <cuda_bf16.h>
#include <math.h>

// Problem constants (fixed shapes for RoIPointPool3d_23845658427905)
#define BB   4
#define NPTS 16384
#define MM   128
#define CF   128
#define SS   512
#define OUTF (3 + CF)   // 131 floats per pooled row
#define BPC  4          // boxes per mask phase (quad)
#define PSPL 4          // point-range splits per quad
#define PPS  (NPTS / PSPL)   // 4096 points per split

// Scratch (device globals — no allocation allowed; zero-initialized at load)
__device__ int g_table[BB * MM * PSPL * SS]; // per (box, split): ordered in-box indices
__device__ int g_cnt[BB * MM * PSPL];        // per (box, split): in-box counts
__device__ int g_done[BB * MM];              // per box: completed-split count (self-resetting)

// ---------------------------------------------------------------------------
// Persistent merged kernel: 512 CTAs (== #boxes == #mask tasks), 512 threads.
// CTA bid:
//   Phase A (mask): quad bid>>2, split bid&3 — tests its 4096 points against
//     the quad's 4 boxes (proven R5 body), publishes tables + counts, then
//     fence + atomicAdd(g_done[box]) for the quad's 4 boxes.
//   Phase B (gather): box bid — producers are CTAs bid&~3..bid|3 (same wave),
//     so the spin is intra-wave skew only. Proven R2 gather body; resets
//     g_done for graph replay after its reads complete.
// Wave-1 gathers (store/DRAM-bound) overlap wave-2 masks (ALU/L2-read-bound).
// ---------------------------------------------------------------------------
__global__ __launch_bounds__(512, 2) void roipool_persist_kernel(
    const float* __restrict__ points,   // (B, N, 3)
    const float* __restrict__ feats,    // (B, N, C)
    const float* __restrict__ boxes,    // (B, M, 7)
    float* __restrict__ out,            // (B, M, S, 131)
    float* __restrict__ flags)          // (B, M)
{
    const int tid  = threadIdx.x;
    const int lane = tid & 31;
    const int w    = tid >> 5;

    // =================== Phase A: MASK (producer) ===================
    {
        const int split = blockIdx.x & (PSPL - 1);
        const int quad  = blockIdx.x >> 2;       // 0..127
        const int bm0   = quad * BPC;            // first box of the quad
        const int b     = bm0 >> 7;              // / MM

        __shared__ float    sprep[BPC * 8];      // cx, cy, czc, hx, hy, hz, ca, sa
        __shared__ unsigned sball[BPC][16][8];
        __shared__ int      wtot[BPC][16];

        if (w == 0 && lane < BPC) {
            const int q = lane;
            const float* bx = boxes + (size_t)(bm0 + q) * 7;
            const float r0 = bx[0], r1 = bx[1], r2 = bx[2];
            const float r3 = bx[3], r4 = bx[4], r5 = bx[5], r6 = bx[6];
            double sv, cv;
            sincos(-(double)r6, &sv, &cv);
            float* o = sprep + q * 8;
            o[0] = r0;
            o[1] = r1;
            o[2] = __fadd_rn(r2, __fmul_rn(0.5f, r5));
            o[3] = __fmul_rn(0.5f, r3);
            o[4] = __fmul_rn(0.5f, r4);
            o[5] = __fmul_rn(0.5f, r5);
            o[6] = (float)cv;
            o[7] = (float)sv;
        }
        __syncthreads();

        float cx[BPC], cy[BPC], cz[BPC], hx[BPC], hy[BPC], hz[BPC], ca[BPC], sa[BPC];
        #pragma unroll
        for (int q = 0; q < BPC; q++) {
            cx[q] = sprep[q * 8 + 0]; cy[q] = sprep[q * 8 + 1];
            cz[q] = sprep[q * 8 + 2]; hx[q] = sprep[q * 8 + 3];
            hy[q] = sprep[q * 8 + 4]; hz[q] = sprep[q * 8 + 5];
            ca[q] = sprep[q * 8 + 6]; sa[q] = sprep[q * 8 + 7];
        }

        const int base_local = split * PPS + w * 256;          // batch-relative
        const float* pb = points + ((size_t)b * NPTS + base_local) * 3;

        int cnt[BPC];
        #pragma unroll
        for (int q = 0; q < BPC; q++) cnt[q] = 0;

        for (int j = 0; j < 8; j++) {
            const int i3 = (j * 32 + lane) * 3;
            const float x = pb[i3 + 0];
            const float y = pb[i3 + 1];
            const float z = pb[i3 + 2];
            #pragma unroll
            for (int q = 0; q < BPC; q++) {
                const float sx = __fsub_rn(x, cx[q]);
                const float sy = __fsub_rn(y, cy[q]);
                const float lx = __fsub_rn(__fmul_rn(sx, ca[q]), __fmul_rn(sy, sa[q]));
                const float ly = __fadd_rn(__fmul_rn(sx, sa[q]), __fmul_rn(sy, ca[q]));
                const float zd = __fsub_rn(z, cz[q]);
                const bool m = (fabsf(zd) <= hz[q]) && (fabsf(lx) < hx[q]) && (fabsf(ly) < hy[q]);
                const unsigned ball = __ballot_sync(0xffffffffu, m);
                if (lane == 0) sball[q][w][j] = ball;
                cnt[q] += __popc(ball);
            }
        }
        if (lane == 0) {
            #pragma unroll
            for (int q = 0; q < BPC; q++) wtot[q][w] = cnt[q];
        }
        __syncthreads();

        const unsigned lt = (1u << lane) - 1u;
        #pragma unroll
        for (int q = 0; q < BPC; q++) {
            int run = 0;
            #pragma unroll
            for (int v = 0; v < 16; v++)
                if (v < w) run += wtot[q][v];
            int* tbl = g_table + (size_t)((bm0 + q) * PSPL + split) * SS;
            #pragma unroll
            for (int j = 0; j < 8; j++) {
                const unsigned ball = sball[q][w][j];
                const int pre = __popc(ball & lt);
                if (((ball >> lane) & 1u) && (run + pre) < SS)
                    tbl[run + pre] = base_local + j * 32 + lane;
                run += __popc(ball);
            }
        }

        if (tid < BPC) {
            int tot = 0;
            #pragma unroll
            for (int v = 0; v < 16; v++) tot += wtot[tid][v];
            g_cnt[(bm0 + tid) * PSPL + split] = tot;
        }

        // publish: make table/cnt visible at gpu scope, then arrive
        __threadfence();
        __syncthreads();
        if (tid < BPC) atomicAdd(&g_done[bm0 + tid], 1);
    }

    // =================== Phase B: GATHER (consumer) ===================
    {
        const int bm = blockIdx.x;           // box id (== bid)
        const int b  = bm >> 7;              // / MM

        __shared__ int sidx[SS];
        __shared__ int pf[4];
        __shared__ int scnt;

        // wait for this box's 4 split producers (same-wave neighbors)
        if (tid == 0) {
            volatile int* vd = g_done;
            while (vd[bm] < PSPL) __nanosleep(32);
            __threadfence();   // acquire
        }
        __syncthreads();

        if (tid == 0) {
            const int c0 = g_cnt[bm * PSPL + 0];
            const int c1 = g_cnt[bm * PSPL + 1];
            const int c2 = g_cnt[bm * PSPL + 2];
            const int c3 = g_cnt[bm * PSPL + 3];
            pf[0] = 0; pf[1] = c0; pf[2] = c0 + c1; pf[3] = c0 + c1 + c2;
            const int tot = c0 + c1 + c2 + c3;
            scnt = tot;
            flags[bm] = (tot == 0) ? 1.0f : 0.0f;
        }
        __syncthreads();
        const int cnt = scnt;

        float* obox = out + (size_t)bm * SS * OUTF;

        if (cnt > 0) {
            const int s = tid;                       // SS == blockDim.x
            const int j = s % cnt;
            const int p = (j >= pf[3]) ? 3 : (j >= pf[2]) ? 2 : (j >= pf[1]) ? 1 : 0;
            sidx[s] = g_table[(size_t)(bm * PSPL + p) * SS + (j - pf[p])];
        }
        __syncthreads();

        // all g_table/g_cnt reads for this box are done: reset for next replay
        if (tid == 0) atomicSub(&g_done[bm], PSPL);

        if (cnt == 0) {
            const float4 zz = make_float4(0.f, 0.f, 0.f, 0.f);
            float4* o4 = (float4*)obox;
            for (int i = tid; i < SS * OUTF / 4; i += 512) o4[i] = zz;
            return;
        }

        const float* pbat = points + (size_t)b * NPTS * 3;
        const float* fbat = feats  + (size_t)b * NPTS * CF;

        // proven R2 gather body: each warp rows s = w, w+16, ...; 2 rows/iter
        for (int s = w; s < SS; s += 32) {
            const int s2  = s + 16;
            const int ia  = sidx[s];
            const int ib  = sidx[s2];
            const float* fa = fbat + (size_t)ia * CF;
            const float* fb = fbat + (size_t)ib * CF;
            const float* pa = pbat + (size_t)ia * 3;
            const float* pb = pbat + (size_t)ib * 3;
            float* oa = obox + (size_t)s  * OUTF;
            float* ob = obox + (size_t)s2 * OUTF;

            const float a0 = (lane < 3) ? pa[lane] : fa[lane - 3];
            const float a1 = fa[lane + 29];
            const float a2 = fa[lane + 61];
            const float a3 = fa[lane + 93];
            float a4 = 0.f; if (lane < 3) a4 = fa[lane + 125];
            const float b0 = (lane < 3) ? pb[lane] : fb[lane - 3];
            const float b1 = fb[lane + 29];
            const float b2 = fb[lane + 61];
            const float b3 = fb[lane + 93];
            float b4 = 0.f; if (lane < 3) b4 = fb[lane + 125];

            oa[lane]       = a0;
            oa[lane + 32]  = a1;
            oa[lane + 64]  = a2;
            oa[lane + 96]  = a3;
            if (lane < 3) oa[lane + 128] = a4;
            ob[lane]       = b0;
            ob[lane + 32]  = b1;
            ob[lane + 64]  = b2;
            ob[lane + 96]  = b3;
            if (lane < 3) ob[lane + 128] = b4;
        }
    }
}

// ---------------------------------------------------------------------------
extern "C" void kernel_launch(void* const* d_in, const int* in_sizes, int n_in,
                              void* d_out, int out_size)
{
    const float* points = (const float*)d_in[0];   // (B, N, 3)
    const float* feats  = (const float*)d_in[1];   // (B, N, C)
    const float* boxes  = (const float*)d_in[2];   // (B, M, 7)

    float* out   = (float*)d_out;
    float* flags = out + (size_t)BB * MM * SS * OUTF;  // empty flags appended

    roipool_persist_kernel<<<BB * MM, 512>>>(points, feats, boxes, out, flags);
}